// round 15
// baseline (speedup 1.0000x reference)
#include <cuda_runtime.h>
#include <math.h>
#include <float.h>

#define NCH 85
#define NTC 6
#define SS  (52 * 52)
#define LOG2E 1.44269504088896340736f
#define MAXCELLS 262144
#define CLS_BLOCKS 1024

// g_acc: [0]=sum_noobj [2]=sum_obj [4]=sum_ciou [5]=sum_box [6]=sum_cls
// all __device__ state zero at load; last cls block resets -> replay-safe.
__device__ double g_acc[7];
__device__ int    g_nobj;
__device__ unsigned int g_done;
__device__ int    g_idx[MAXCELLS];

__device__ __forceinline__ float warp_sum(float v) {
#pragma unroll
    for (int o = 16; o; o >>= 1) v += __shfl_xor_sync(0xffffffffu, v, o);
    return v;
}

// FFMA-pipe exp2: magic-number round + degree-5 poly (|x| small here).
__device__ __forceinline__ float fast_exp2(float x) {
    float r  = x + 12582912.0f;                 // 1.5 * 2^23
    int   ik = __float_as_int(r) - 0x4B400000;
    float f  = x - (r - 12582912.0f);           // f in [-0.5, 0.5]
    float p  = 1.3333558e-3f;
    p = fmaf(p, f, 9.6181291e-3f);
    p = fmaf(p, f, 5.5504109e-2f);
    p = fmaf(p, f, 2.4022651e-1f);
    p = fmaf(p, f, 6.9314718e-1f);
    p = fmaf(p, f, 1.0f);
    return p * __int_as_float((ik + 127) << 23);
}

// FFMA-pipe natural log for x > 0 (cephes-style, ~1e-7 rel).
__device__ __forceinline__ float fast_ln(float x) {
    const int bits = __float_as_int(x);
    const int e    = (bits - 0x3f3504f3) >> 23;            // sqrt(0.5) centering
    const float m  = __int_as_float(bits - (e << 23));     // [0.7071, 1.4142)
    const float f  = m - 1.0f;
    const float z  = f * f;
    float p = 7.0376836292e-2f;
    p = fmaf(p, f, -1.1514610310e-1f);
    p = fmaf(p, f,  1.1676998740e-1f);
    p = fmaf(p, f, -1.2420140846e-1f);
    p = fmaf(p, f,  1.4249322787e-1f);
    p = fmaf(p, f, -1.6668057665e-1f);
    p = fmaf(p, f,  2.0000714765e-1f);
    p = fmaf(p, f, -2.4999993993e-1f);
    p = fmaf(p, f,  3.3333331174e-1f);
    const float r = fmaf(f * z, p, fmaf(-0.5f, z, f));
    return fmaf((float)e, 0.69314718055994531f, r);
}

// atan(x) for x > 0: range-reduce to [0,1], 6-term minimax (abs err ~2e-7).
__device__ __forceinline__ float fatan_pos(float x) {
    const bool big = (x > 1.0f);
    const float t = big ? __fdividef(1.0f, x) : x;
    const float s = t * t;
    float p = -1.1721200e-2f;
    p = fmaf(p, s,  5.2653322e-2f);
    p = fmaf(p, s, -1.1643287e-1f);
    p = fmaf(p, s,  1.9354346e-1f);
    p = fmaf(p, s, -3.3262347e-1f);
    p = fmaf(p, s,  9.9997726e-1f);
    const float r = t * p;
    return big ? (1.57079632679f - r) : r;
}

__device__ __forceinline__ float sigmoidf_(float x) {
    return 1.0f / (1.0f + __expf(-x));
}

// ── Phase A: stream noobj + obj scalar losses + compaction (one pass) ─────
__global__ __launch_bounds__(256)
void scan_kernel(const float* __restrict__ pred,
                 const float* __restrict__ tgt,
                 const float* __restrict__ anc,
                 int ncells) {
    const int lane = threadIdx.x & 31;
    const int wib  = threadIdx.x >> 5;
    const int c    = blockIdx.x * 256 + threadIdx.x;
    const bool valid = (c < ncells);

    const float t0  = valid ? __ldg(tgt + (size_t)c * NTC) : -1.0f;
    const float p0  = valid ? __ldg(pred + (size_t)c * NCH) : 0.0f;

    float s_noobj = 0.f, s_obj = 0.f, s_ciou = 0.f, s_box = 0.f;

    if (t0 == 0.0f)
        s_noobj = fmaxf(p0, 0.0f) + __logf(1.0f + __expf(-fabsf(p0)));

    if (t0 == 1.0f) {
        // obj scalar losses, computed here (data is already resident/near)
        const float* p = pred + (size_t)c * NCH;
        const float* t = tgt  + (size_t)c * NTC;
        const float p1 = __ldg(p + 1);
        const float p2 = __ldg(p + 2);
        const float p3 = __ldg(p + 3);
        const float p4 = __ldg(p + 4);
        const float2 t01 = __ldg((const float2*)(t + 0));
        const float2 t23 = __ldg((const float2*)(t + 2));
        const float  t4v = __ldg(t + 4);
        const float t1 = t01.y, t2 = t23.x, t3 = t23.y, t4 = t4v;

        const float a0w = __ldg(anc + 0), a0h = __ldg(anc + 1);
        const float a1w = __ldg(anc + 2), a1h = __ldg(anc + 3);
        const float a2w = __ldg(anc + 4), a2h = __ldg(anc + 5);
        const int a = (c / SS) % 3;
        const float aw = (a == 0) ? a0w : ((a == 1) ? a1w : a2w);
        const float ah = (a == 0) ? a0h : ((a == 1) ? a1h : a2h);

        const float sx = sigmoidf_(p1);
        const float sy = sigmoidf_(p2);
        const float bw = __expf(p3) * aw;
        const float bh = __expf(p4) * ah;

        const float b1x1 = sx - 0.5f * bw, b1x2 = sx + 0.5f * bw;
        const float b1y1 = sy - 0.5f * bh, b1y2 = sy + 0.5f * bh;
        const float b2x1 = t1 - 0.5f * t3, b2x2 = t1 + 0.5f * t3;
        const float b2y1 = t2 - 0.5f * t4, b2y2 = t2 + 0.5f * t4;
        const float iw = fmaxf(fminf(b1x2, b2x2) - fmaxf(b1x1, b2x1), 0.0f);
        const float ih = fmaxf(fminf(b1y2, b2y2) - fmaxf(b1y1, b2y1), 0.0f);
        const float inter = iw * ih;
        const float area1 = fabsf(bw * bh);
        const float area2 = fabsf(t3 * t4);
        const float iou_m = inter / (area1 + area2 - inter + 1e-6f);

        s_obj = fmaxf(p0, 0.0f) - p0 * iou_m + __logf(1.0f + __expf(-fabsf(p0)));

        const float uni  = bw * bh + t3 * t4 - inter;
        const float iou  = inter / (uni + 1e-7f);
        const float cw   = fmaxf(b1x2, b2x2) - fminf(b1x1, b2x1);
        const float chh  = fmaxf(b1y2, b2y2) - fminf(b1y1, b2y1);
        const float diag = cw * cw + chh * chh + 1e-7f;
        const float dx   = sx - t1;
        const float dy   = sy - t2;
        const float diou = 1.0f - iou + (dx * dx + dy * dy) / diag;
        const float dat  = fatan_pos(t3 / (t4 + 1e-7f)) - fatan_pos(bw / (bh + 1e-7f));
        const float vv   = 0.40528473456f * dat * dat;   // 4/pi^2
        const float alpha = vv / (1.0f - iou + vv + 1e-7f);
        s_ciou = diou + alpha * vv;

        const float lw = __logf(1e-16f + t3 / aw);
        const float lh = __logf(1e-16f + t4 / ah);
        const float d1 = sx - t1, d2 = sy - t2, d3 = p3 - lw, d4 = p4 - lh;
        s_box = d1 * d1 + d2 * d2 + d3 * d3 + d4 * d4;
    }

    // compaction (warp ballot -> block scan -> one atomic)
    const unsigned om = __ballot_sync(0xffffffffu, t0 == 1.0f);
    const int wcount  = __popc(om);

    __shared__ int   wcnt[8];
    __shared__ int   blk_base;
    __shared__ float sred[4][8];

    s_noobj = warp_sum(s_noobj);
    s_obj   = warp_sum(s_obj);
    s_ciou  = warp_sum(s_ciou);
    s_box   = warp_sum(s_box);
    if (lane == 0) {
        wcnt[wib] = wcount;
        sred[0][wib] = s_noobj; sred[1][wib] = s_obj;
        sred[2][wib] = s_ciou;  sred[3][wib] = s_box;
    }
    __syncthreads();

    if (threadIdx.x == 0) {
        int tot = 0;
#pragma unroll
        for (int w = 0; w < 8; w++) { int t = wcnt[w]; wcnt[w] = tot; tot += t; }
        blk_base = tot ? atomicAdd(&g_nobj, tot) : 0;
    }
    if (threadIdx.x < 4) {
        float s = 0.f;
#pragma unroll
        for (int w = 0; w < 8; w++) s += sred[threadIdx.x][w];
        static const int map[4] = {0, 2, 4, 5};
        atomicAdd(&g_acc[map[threadIdx.x]], (double)s);
    }
    __syncthreads();

    if (t0 == 1.0f) {
        const int pos = blk_base + wcnt[wib] + __popc(om & ((1u << lane) - 1u));
        g_idx[pos] = c;
    }
}

// ── Phase B: class NLL only, warp-per-cell with ILP2 ──────────────────────
__global__ __launch_bounds__(256)
void cls_kernel(const float* __restrict__ pred,
                const float* __restrict__ tgt,
                int ncells, float* __restrict__ out) {
    const int lane   = threadIdx.x & 31;
    const int gwarp  = (blockIdx.x * blockDim.x + threadIdx.x) >> 5;
    const int nwarps = (gridDim.x * blockDim.x) >> 5;
    const int nobj   = g_nobj;

    float s_cls = 0.f;

    for (int i = gwarp * 2; i < nobj; i += nwarps * 2) {
        const bool haveB = (i + 1 < nobj);
        const int cellA = g_idx[i];
        const int cellB = g_idx[haveB ? (i + 1) : i];
        const float* pa = pred + (size_t)cellA * NCH;
        const float* pb = pred + (size_t)cellB * NCH;

        // both cells' loads issue together -> MLP 8
        const float a0 = __ldg(pa + lane);
        const float a1 = __ldg(pa + 32 + lane);
        const float a2 = (lane < 21) ? __ldg(pa + 64 + lane) : 0.0f;
        const float b0 = __ldg(pb + lane);
        const float b1 = __ldg(pb + 32 + lane);
        const float b2 = (lane < 21) ? __ldg(pb + 64 + lane) : 0.0f;
        const float t5a = __ldg(tgt + (size_t)cellA * NTC + 5);
        const float t5b = __ldg(tgt + (size_t)cellB * NTC + 5);

        float ea = fast_exp2(a1 * LOG2E);
        float eb = fast_exp2(b1 * LOG2E);
        if (lane >= 5) { ea += fast_exp2(a0 * LOG2E); eb += fast_exp2(b0 * LOG2E); }
        if (lane < 21) { ea += fast_exp2(a2 * LOG2E); eb += fast_exp2(b2 * LOG2E); }

        // two independent reduction trees, interleaved by the compiler
        float va = ea, vb = eb;
#pragma unroll
        for (int o = 16; o; o >>= 1) {
            va += __shfl_xor_sync(0xffffffffu, va, o);
            vb += __shfl_xor_sync(0xffffffffu, vb, o);
        }

        const int lA = 5 + (int)t5a;
        const int lB = 5 + (int)t5b;
        const float xa0 = __shfl_sync(0xffffffffu, a0, lA & 31);
        const float xa1 = __shfl_sync(0xffffffffu, a1, lA & 31);
        const float xa2 = __shfl_sync(0xffffffffu, a2, lA & 31);
        const float xb0 = __shfl_sync(0xffffffffu, b0, lB & 31);
        const float xb1 = __shfl_sync(0xffffffffu, b1, lB & 31);
        const float xb2 = __shfl_sync(0xffffffffu, b2, lB & 31);
        const float xlA = (lA < 32) ? xa0 : ((lA < 64) ? xa1 : xa2);
        const float xlB = (lB < 32) ? xb0 : ((lB < 64) ? xb1 : xb2);

        s_cls += fast_ln(va) - xlA;
        if (haveB) s_cls += fast_ln(vb) - xlB;
    }

    // s_cls is warp-uniform
    __shared__ float sm[8];
    const int wib = threadIdx.x >> 5;
    if (lane == 0) sm[wib] = s_cls;
    __syncthreads();
    if (threadIdx.x == 0) {
        float s = 0.f;
        const int nw = blockDim.x >> 5;
        for (int w = 0; w < nw; w++) s += sm[w];
        atomicAdd(&g_acc[6], (double)s);
    }
    __threadfence();

    // last-block finalize + state reset
    __shared__ int is_last;
    if (threadIdx.x == 0) {
        unsigned prev = atomicAdd(&g_done, 1u);
        is_last = (prev == gridDim.x - 1u) ? 1 : 0;
    }
    __syncthreads();
    if (is_last && threadIdx.x == 0) {
        const double nobjd  = (double)nobj;
        const double cobj   = fmax(nobjd, 1.0);
        const double cnoobj = fmax((double)ncells - nobjd, 1.0);
        const double noobj  = g_acc[0] / cnoobj;
        const double objl   = g_acc[2] / cobj;
        const double cioul  = g_acc[4] / cobj;
        const double boxl   = (g_acc[5] / cobj) * 0.25;
        const double clsl   = g_acc[6] / cobj;
        out[0] = (float)(10.0 * boxl + 10.0 * objl + noobj + clsl + cioul);
#pragma unroll
        for (int k = 0; k < 7; k++) g_acc[k] = 0.0;
        g_nobj = 0;
        __threadfence();
        g_done = 0;
    }
}

extern "C" void kernel_launch(void* const* d_in, const int* in_sizes, int n_in,
                              void* d_out, int out_size) {
    int ip = 0, it = 1, ia = 2;
    long best = -1;
    for (int i = 0; i < n_in; i++) {
        if (in_sizes[i] == 6) ia = i;
        if ((long)in_sizes[i] > best) { best = in_sizes[i]; ip = i; }
    }
    for (int i = 0; i < n_in; i++) if (i != ip && i != ia) it = i;

    const float* pred = (const float*)d_in[ip];
    const float* tgt  = (const float*)d_in[it];
    const float* anc  = (const float*)d_in[ia];
    const int ncells  = in_sizes[ip] / NCH;

    const int nblkA = (ncells + 255) / 256;
    scan_kernel<<<nblkA, 256>>>(pred, tgt, anc, ncells);
    cls_kernel<<<CLS_BLOCKS, 256>>>(pred, tgt, ncells, (float*)d_out);
}